// round 6
// baseline (speedup 1.0000x reference)
#include <cuda_runtime.h>
#include <cuda_bf16.h>
#include <cstdint>

// VectorQuantizer — bf16 mma.sync screening + exact fp32 rescoring that
// bit-replicates the reference numerics:
//   dist_k = fl( fl(||z||^2 + ||e_k||^2) - 2*C_k ), C_k = ascending-d fmaf chain from 0
//   argmin first-index tie-break; Zq = fl(z + fl(e-z)); loss = 1.25*mean((e-z)^2)

typedef unsigned int u32;

#define DDIM 64
#define KC 512
#define HW 4096
#define CHW 262144
#define NVEC 131072
#define THREADS 256
#define WARPS 8
#define GRID 148
#define TILE 256                 // vectors per tile
#define NTILES (NVEC / TILE)     // 512
#define ZQ_ELEMS 8388608
#define CAP 6

__device__ float g_blocksums[GRID];
__device__ unsigned int g_done = 0;

// dynamic smem layout
struct Smem {
    uint2 Bfrag[64 * 4 * 32];    // [ntile][ks][lane], 64KB
    float zfp[DDIM * TILE];      // [d][vector], 64KB
    float Bsh[KC];               // exact ||e_k||^2
    float An[TILE];              // exact ||z||^2 per vector
    int   kwin[TILE];
    float red[WARPS];
    float Bmax;
};
#define SMEM_TOTAL ((int)sizeof(Smem))

__device__ __forceinline__ u32 packbf(float lo, float hi) {
    u32 r; asm("cvt.rn.bf16x2.f32 %0, %1, %2;" : "=r"(r) : "f"(hi), "f"(lo)); return r;
}
__device__ __forceinline__ void mma16816(float c[4], const u32 a[4], const u32 b0, const u32 b1) {
    asm volatile(
        "mma.sync.aligned.m16n8k16.row.col.f32.bf16.bf16.f32 "
        "{%0,%1,%2,%3}, {%4,%5,%6,%7}, {%8,%9}, {%0,%1,%2,%3};"
        : "+f"(c[0]), "+f"(c[1]), "+f"(c[2]), "+f"(c[3])
        : "r"(a[0]), "r"(a[1]), "r"(a[2]), "r"(a[3]), "r"(b0), "r"(b1));
}

__global__ void __launch_bounds__(THREADS, 1)
vq_mma_kernel(const float* __restrict__ inp, const float* __restrict__ E,
              float* __restrict__ out, int zq_off)
{
    extern __shared__ char smraw[];
    Smem* sh = (Smem*)smraw;

    const int tid = threadIdx.x;
    const int warp = tid >> 5;
    const int lane = tid & 31;
    const int m4 = lane & 3;
    const int qrow = lane >> 2;

    // ---- one-time staging: B fragments (bf16) + exact Bsh + Bmax ----
    for (int idx = tid; idx < 64 * 4 * 32; idx += THREADS) {
        int l = idx & 31, ks = (idx >> 5) & 3, nt = idx >> 7;
        int kc = nt * 8 + (l >> 2);
        int d0 = ks * 16 + 2 * (l & 3);
        const float* er = E + kc * DDIM;
        uint2 v;
        v.x = packbf(er[d0],     er[d0 + 1]);
        v.y = packbf(er[d0 + 8], er[d0 + 9]);
        sh->Bfrag[idx] = v;
    }
    for (int k = tid; k < KC; k += THREADS) {      // exact ||e||^2, R2-verbatim form
        const float* er = E + k * DDIM;
        float bsum = 0.f;
        #pragma unroll
        for (int d = 0; d < DDIM; d++) { float e = er[d]; bsum = bsum + e * e; }
        sh->Bsh[k] = bsum;
    }
    __syncthreads();
    if (tid == 0) {
        float m = 0.f;
        for (int k = 0; k < KC; k++) m = fmaxf(m, sh->Bsh[k]);
        sh->Bmax = m;
    }
    __syncthreads();
    const float Bmax = sh->Bmax;

    float ls = 0.f;

    for (int tile = blockIdx.x; tile < NTILES; tile += GRID) {
        const int base = tile * TILE;
        const int b = base >> 12, hw0 = base & 4095;
        const float* zsrc = inp + (size_t)b * CHW + hw0;

        __syncthreads();   // protect zfp/An/kwin reuse across tiles
        // stage z (coalesced) + exact ||z||^2 (ascending d, R2-verbatim form)
        #pragma unroll 8
        for (int d = 0; d < DDIM; d++)
            sh->zfp[d * TILE + tid] = __ldg(zsrc + (size_t)d * HW + tid);
        __syncthreads();
        {
            float A = 0.f;
            #pragma unroll
            for (int d = 0; d < DDIM; d++) { float a = sh->zfp[d * TILE + tid]; A = A + a * a; }
            sh->An[tid] = A;
        }
        __syncthreads();

        // ---- A fragments for this warp's 32 vectors (2 m-tiles) ----
        u32 afr[2][4][4];
        const int r0g = warp * 32 + qrow;
        #pragma unroll
        for (int m = 0; m < 2; m++) {
            const int rA = r0g + m * 16, rB = rA + 8;
            #pragma unroll
            for (int ks = 0; ks < 4; ks++) {
                const int d0 = ks * 16 + 2 * m4;
                afr[m][ks][0] = packbf(sh->zfp[d0 * TILE + rA],       sh->zfp[(d0 + 1) * TILE + rA]);
                afr[m][ks][1] = packbf(sh->zfp[d0 * TILE + rB],       sh->zfp[(d0 + 1) * TILE + rB]);
                afr[m][ks][2] = packbf(sh->zfp[(d0 + 8) * TILE + rA], sh->zfp[(d0 + 9) * TILE + rA]);
                afr[m][ks][3] = packbf(sh->zfp[(d0 + 8) * TILE + rB], sh->zfp[(d0 + 9) * TILE + rB]);
            }
        }

        // per-thread rows: j=0: r0g, j=1: r0g+8, j=2: r0g+16, j=3: r0g+24
        int rowid[4]; float Arow[4], marg[4];
        #pragma unroll
        for (int j = 0; j < 4; j++) {
            rowid[j] = r0g + (j >> 1) * 16 + (j & 1) * 8;
            Arow[j] = sh->An[rowid[j]];
            marg[j] = 0.025f * sqrtf(Arow[j] * Bmax) + 5e-5f;
        }

        float runmin[4]; int cnt[4], ovf[4];
        int candk[4][CAP]; float cands[4][CAP];
        #pragma unroll
        for (int j = 0; j < 4; j++) { runmin[j] = 3.402823466e38f; cnt[j] = 0; ovf[j] = 0; }

        #define UPD(j, sv, kv) do { \
            float _s = (sv); int _k = (kv); \
            if (_s < runmin[j]) runmin[j] = _s; \
            if (_s <= runmin[j] + marg[j]) { \
                if (cnt[j] == CAP) { \
                    int _nc = 0; float _th = runmin[j] + marg[j]; \
                    for (int _i = 0; _i < CAP; _i++) \
                        if (cands[j][_i] <= _th) { candk[j][_nc] = candk[j][_i]; cands[j][_nc] = cands[j][_i]; _nc++; } \
                    cnt[j] = _nc; \
                } \
                if (cnt[j] < CAP) { candk[j][cnt[j]] = _k; cands[j][cnt[j]] = _s; cnt[j]++; } \
                else ovf[j] = 1; \
            } \
        } while (0)

        // ---- screening: 64 n-tiles of 8 codes ----
        #pragma unroll 2
        for (int nt = 0; nt < 64; nt++) {
            uint2 bf0 = sh->Bfrag[(nt * 4 + 0) * 32 + lane];
            uint2 bf1 = sh->Bfrag[(nt * 4 + 1) * 32 + lane];
            uint2 bf2 = sh->Bfrag[(nt * 4 + 2) * 32 + lane];
            uint2 bf3 = sh->Bfrag[(nt * 4 + 3) * 32 + lane];
            float c0[4] = {0.f, 0.f, 0.f, 0.f};
            float c1[4] = {0.f, 0.f, 0.f, 0.f};
            mma16816(c0, afr[0][0], bf0.x, bf0.y);  mma16816(c1, afr[1][0], bf0.x, bf0.y);
            mma16816(c0, afr[0][1], bf1.x, bf1.y);  mma16816(c1, afr[1][1], bf1.x, bf1.y);
            mma16816(c0, afr[0][2], bf2.x, bf2.y);  mma16816(c1, afr[1][2], bf2.x, bf2.y);
            mma16816(c0, afr[0][3], bf3.x, bf3.y);  mma16816(c1, afr[1][3], bf3.x, bf3.y);

            const int k0 = nt * 8 + 2 * m4;
            const float B0 = sh->Bsh[k0], B1 = sh->Bsh[k0 + 1];
            UPD(0, fmaf(-2.f, c0[0], B0), k0); UPD(0, fmaf(-2.f, c0[1], B1), k0 + 1);
            UPD(1, fmaf(-2.f, c0[2], B0), k0); UPD(1, fmaf(-2.f, c0[3], B1), k0 + 1);
            UPD(2, fmaf(-2.f, c1[0], B0), k0); UPD(2, fmaf(-2.f, c1[1], B1), k0 + 1);
            UPD(3, fmaf(-2.f, c1[2], B0), k0); UPD(3, fmaf(-2.f, c1[3], B1), k0 + 1);
        }
        #undef UPD

        // ---- per row: group-of-4 min, exact rescore survivors, lexicographic reduce ----
        #pragma unroll
        for (int j = 0; j < 4; j++) {
            float gm = runmin[j];
            gm = fminf(gm, __shfl_xor_sync(0xffffffffu, gm, 1, 4));
            gm = fminf(gm, __shfl_xor_sync(0xffffffffu, gm, 2, 4));
            const float thr = gm + marg[j];
            const int row = rowid[j];

            float bestS = 3.402823466e38f; int bestk = 0x7fffffff;
            if (ovf[j]) {
                // fallback: exact scan of this lane's 128 codes (ascending k, strict <)
                for (int nt = 0; nt < 64; nt++) {
                    #pragma unroll
                    for (int jj = 0; jj < 2; jj++) {
                        const int k = nt * 8 + 2 * m4 + jj;
                        const float* er = E + k * DDIM;
                        float C = 0.f;
                        #pragma unroll
                        for (int d = 0; d < DDIM; d++)
                            C = fmaf(sh->zfp[d * TILE + row], __ldg(er + d), C);
                        float S = fmaf(-2.f, C, Arow[j] + sh->Bsh[k]);
                        if (S < bestS) { bestS = S; bestk = k; }
                    }
                }
            } else {
                for (int i = 0; i < cnt[j]; i++) {
                    if (cands[j][i] > thr) continue;
                    const int k = candk[j][i];
                    const float* er = E + k * DDIM;
                    float C = 0.f;
                    #pragma unroll
                    for (int d = 0; d < DDIM; d++)
                        C = fmaf(sh->zfp[d * TILE + row], __ldg(er + d), C);
                    float S = fmaf(-2.f, C, Arow[j] + sh->Bsh[k]);
                    if (S < bestS || (S == bestS && k < bestk)) { bestS = S; bestk = k; }
                }
            }
            // lexicographic (S, k) min across the 4 lanes sharing this row
            #pragma unroll
            for (int off = 1; off <= 2; off <<= 1) {
                float oS = __shfl_xor_sync(0xffffffffu, bestS, off, 4);
                int   ok = __shfl_xor_sync(0xffffffffu, bestk, off, 4);
                if (oS < bestS || (oS == bestS && ok < bestk)) { bestS = oS; bestk = ok; }
            }
            if (m4 == 0) sh->kwin[row] = bestk;
        }
        __syncthreads();

        // ---- emit: thread owns vector tid; coalesced stores ----
        {
            const int k = sh->kwin[tid];
            const float* er = E + k * DDIM;
            float* o = out + zq_off + (size_t)b * CHW + hw0 + tid;
            #pragma unroll
            for (int d = 0; d < DDIM; d++) {
                float zv = sh->zfp[d * TILE + tid];
                float t = er[d] - zv;              // fl(e - z), R2-verbatim
                ls += t * t;
                o[(size_t)d * HW] = zv + t;        // fl(z + fl(e-z))
            }
        }
    }

    // ---- deterministic loss reduction + fused finalize ----
    #pragma unroll
    for (int off = 16; off; off >>= 1) ls += __shfl_down_sync(0xffffffffu, ls, off);
    if (lane == 0) sh->red[warp] = ls;
    __syncthreads();
    __shared__ unsigned int s_rank;
    if (tid == 0) {
        float t = 0.f;
        #pragma unroll
        for (int i = 0; i < WARPS; i++) t += sh->red[i];
        g_blocksums[blockIdx.x] = t;
        __threadfence();
        s_rank = atomicAdd(&g_done, 1u);
    }
    __syncthreads();
    if (s_rank == GRID - 1) {
        if (tid < 32) {
            double s = 0.0;
            for (int i = tid; i < GRID; i += 32) s += (double)g_blocksums[i];
            #pragma unroll
            for (int off = 16; off; off >>= 1) s += __shfl_down_sync(0xffffffffu, s, off);
            if (tid == 0) {
                if (zq_off >= 1) out[0] = (float)(s * (1.25 / 8388608.0));
                g_done = 0;   // reset for next graph replay
            }
        }
    }
}

extern "C" void kernel_launch(void* const* d_in, const int* in_sizes, int n_in,
                              void* d_out, int out_size)
{
    const float* inp = (const float*)d_in[0];  // [32,64,64,64] fp32
    const float* E   = (const float*)d_in[1];  // [512,64] fp32
    float* out = (float*)d_out;

    int zq_off = (out_size > ZQ_ELEMS) ? (out_size - ZQ_ELEMS) : 0;

    cudaFuncSetAttribute(vq_mma_kernel, cudaFuncAttributeMaxDynamicSharedMemorySize, SMEM_TOTAL);
    vq_mma_kernel<<<GRID, THREADS, SMEM_TOTAL>>>(inp, E, out, zq_off);
}

// round 7
// speedup vs baseline: 1.5212x; 1.5212x over previous
#include <cuda_runtime.h>
#include <cuda_bf16.h>
#include <cstdint>

// VectorQuantizer — bf16 mma.sync screening (two-pass, branch-light, no local mem)
// + exact fp32 rescoring that bit-replicates the reference numerics:
//   dist_k = fl( fl(||z||^2 + ||e_k||^2) - 2*C_k ), C_k = ascending-d fmaf chain from 0
//   argmin first-index tie-break; Zq = fl(z + fl(e-z)); loss = 1.25*mean((e-z)^2)

typedef unsigned int u32;

#define DDIM 64
#define KC 512
#define HW 4096
#define CHW 262144
#define NVEC 131072
#define THREADS 256
#define WARPS 8
#define GRID 148
#define TILE 256                 // vectors per tile
#define NTILES (NVEC / TILE)     // 512
#define ZQ_ELEMS 8388608

__device__ float g_blocksums[GRID];
__device__ unsigned int g_done = 0;

struct Smem {
    uint2 Bfrag[64 * 4 * 32];    // [ntile][ks][lane], 64KB bf16 fragments
    float zfp[DDIM * TILE];      // [d][vector], 64KB exact z
    float Bsh[KC];               // exact ||e_k||^2
    float An[TILE];              // exact ||z||^2
    int   kwin[TILE];
    float red[WARPS];
    float Bmax;
};
#define SMEM_TOTAL ((int)sizeof(Smem))

__device__ __forceinline__ u32 packbf(float lo, float hi) {
    u32 r; asm("cvt.rn.bf16x2.f32 %0, %1, %2;" : "=r"(r) : "f"(hi), "f"(lo)); return r;
}
__device__ __forceinline__ void mma16816(float c[4], const u32 a[4], const u32 b0, const u32 b1) {
    asm volatile(
        "mma.sync.aligned.m16n8k16.row.col.f32.bf16.bf16.f32 "
        "{%0,%1,%2,%3}, {%4,%5,%6,%7}, {%8,%9}, {%0,%1,%2,%3};"
        : "+f"(c[0]), "+f"(c[1]), "+f"(c[2]), "+f"(c[3])
        : "r"(a[0]), "r"(a[1]), "r"(a[2]), "r"(a[3]), "r"(b0), "r"(b1));
}

// 8 approx scores for n-tile nt: sc[j*2+c] = row j's score for code k0+c mapping
__device__ __forceinline__ void score8(const Smem* sh, const u32 afr[2][4][4],
                                       int nt, int lane, int m4, float sc[8]) {
    uint2 bf0 = sh->Bfrag[(nt * 4 + 0) * 32 + lane];
    uint2 bf1 = sh->Bfrag[(nt * 4 + 1) * 32 + lane];
    uint2 bf2 = sh->Bfrag[(nt * 4 + 2) * 32 + lane];
    uint2 bf3 = sh->Bfrag[(nt * 4 + 3) * 32 + lane];
    float c0[4] = {0.f, 0.f, 0.f, 0.f};
    float c1[4] = {0.f, 0.f, 0.f, 0.f};
    mma16816(c0, afr[0][0], bf0.x, bf0.y);  mma16816(c1, afr[1][0], bf0.x, bf0.y);
    mma16816(c0, afr[0][1], bf1.x, bf1.y);  mma16816(c1, afr[1][1], bf1.x, bf1.y);
    mma16816(c0, afr[0][2], bf2.x, bf2.y);  mma16816(c1, afr[1][2], bf2.x, bf2.y);
    mma16816(c0, afr[0][3], bf3.x, bf3.y);  mma16816(c1, afr[1][3], bf3.x, bf3.y);
    const int k0 = nt * 8 + 2 * m4;
    const float B0 = sh->Bsh[k0], B1 = sh->Bsh[k0 + 1];
    sc[0] = fmaf(-2.f, c0[0], B0);  sc[1] = fmaf(-2.f, c0[1], B1);   // row j=0
    sc[2] = fmaf(-2.f, c0[2], B0);  sc[3] = fmaf(-2.f, c0[3], B1);   // row j=1
    sc[4] = fmaf(-2.f, c1[0], B0);  sc[5] = fmaf(-2.f, c1[1], B1);   // row j=2
    sc[6] = fmaf(-2.f, c1[2], B0);  sc[7] = fmaf(-2.f, c1[3], B1);   // row j=3
}

// exact rescore (reference numerics) + lexicographic (S,k) update — rare path
__device__ __noinline__ void exact_update(const Smem* sh, const float* __restrict__ E,
                                          int row, int k, float A, float& bestS, int& bestk) {
    const float* er = E + k * DDIM;
    float C = 0.f;
    #pragma unroll 8
    for (int d = 0; d < DDIM; d++) C = fmaf(sh->zfp[d * TILE + row], __ldg(er + d), C);
    float S = fmaf(-2.f, C, A + sh->Bsh[k]);
    if (S < bestS || (S == bestS && k < bestk)) { bestS = S; bestk = k; }
}

__global__ void __launch_bounds__(THREADS, 1)
vq_mma_kernel(const float* __restrict__ inp, const float* __restrict__ E,
              float* __restrict__ out, int zq_off)
{
    extern __shared__ char smraw[];
    Smem* sh = (Smem*)smraw;

    const int tid = threadIdx.x;
    const int warp = tid >> 5;
    const int lane = tid & 31;
    const int m4 = lane & 3;
    const int qrow = lane >> 2;

    // ---- one-time staging: B fragments (bf16) + exact Bsh + Bmax ----
    for (int idx = tid; idx < 64 * 4 * 32; idx += THREADS) {
        int l = idx & 31, ks = (idx >> 5) & 3, nt = idx >> 7;
        int kc = nt * 8 + (l >> 2);
        int d0 = ks * 16 + 2 * (l & 3);
        const float* er = E + kc * DDIM;
        uint2 v;
        v.x = packbf(er[d0],     er[d0 + 1]);
        v.y = packbf(er[d0 + 8], er[d0 + 9]);
        sh->Bfrag[idx] = v;
    }
    for (int k = tid; k < KC; k += THREADS) {      // exact ||e||^2 (R2-verbatim)
        const float* er = E + k * DDIM;
        float bsum = 0.f;
        #pragma unroll
        for (int d = 0; d < DDIM; d++) { float e = er[d]; bsum = bsum + e * e; }
        sh->Bsh[k] = bsum;
    }
    __syncthreads();
    if (tid == 0) {
        float m = 0.f;
        for (int k = 0; k < KC; k++) m = fmaxf(m, sh->Bsh[k]);
        sh->Bmax = m;
    }
    __syncthreads();
    const float Bmax = sh->Bmax;

    float ls = 0.f;

    for (int tile = blockIdx.x; tile < NTILES; tile += GRID) {
        const int base = tile * TILE;
        const int b = base >> 12, hw0 = base & 4095;
        const float* zsrc = inp + (size_t)b * CHW + hw0;

        __syncthreads();   // protect zfp/An/kwin reuse across tiles
        #pragma unroll 8
        for (int d = 0; d < DDIM; d++)
            sh->zfp[d * TILE + tid] = __ldg(zsrc + (size_t)d * HW + tid);
        __syncthreads();
        {
            float A = 0.f;   // exact ||z||^2 ascending d (R2-verbatim)
            #pragma unroll
            for (int d = 0; d < DDIM; d++) { float a = sh->zfp[d * TILE + tid]; A = A + a * a; }
            sh->An[tid] = A;
        }
        __syncthreads();

        // ---- A fragments (this warp's 32 vectors, 2 m-tiles) ----
        u32 afr[2][4][4];
        const int r0g = warp * 32 + qrow;
        #pragma unroll
        for (int m = 0; m < 2; m++) {
            const int rA = r0g + m * 16, rB = rA + 8;
            #pragma unroll
            for (int ks = 0; ks < 4; ks++) {
                const int d0 = ks * 16 + 2 * m4;
                afr[m][ks][0] = packbf(sh->zfp[d0 * TILE + rA],       sh->zfp[(d0 + 1) * TILE + rA]);
                afr[m][ks][1] = packbf(sh->zfp[d0 * TILE + rB],       sh->zfp[(d0 + 1) * TILE + rB]);
                afr[m][ks][2] = packbf(sh->zfp[(d0 + 8) * TILE + rA], sh->zfp[(d0 + 9) * TILE + rA]);
                afr[m][ks][3] = packbf(sh->zfp[(d0 + 8) * TILE + rB], sh->zfp[(d0 + 9) * TILE + rB]);
            }
        }

        int rowid[4]; float Arow[4];
        #pragma unroll
        for (int j = 0; j < 4; j++) {
            rowid[j] = r0g + (j >> 1) * 16 + (j & 1) * 8;
            Arow[j] = sh->An[rowid[j]];
        }

        // ---- pass 1: branchless running min ----
        float runmin[4] = {3.402823466e38f, 3.402823466e38f, 3.402823466e38f, 3.402823466e38f};
        #pragma unroll 2
        for (int nt = 0; nt < 64; nt++) {
            float sc[8];
            score8(sh, afr, nt, lane, m4, sc);
            #pragma unroll
            for (int j = 0; j < 4; j++)
                runmin[j] = fminf(runmin[j], fminf(sc[2 * j], sc[2 * j + 1]));
        }
        float thr[4];
        #pragma unroll
        for (int j = 0; j < 4; j++) {
            float gm = runmin[j];
            gm = fminf(gm, __shfl_xor_sync(0xffffffffu, gm, 1, 4));
            gm = fminf(gm, __shfl_xor_sync(0xffffffffu, gm, 2, 4));
            thr[j] = gm + (0.025f * sqrtf(Arow[j] * Bmax) + 5e-5f);
        }

        // ---- pass 2: recompute, exact-rescore the rare in-margin hits inline ----
        float bestS[4] = {3.402823466e38f, 3.402823466e38f, 3.402823466e38f, 3.402823466e38f};
        int bestk[4] = {0x7fffffff, 0x7fffffff, 0x7fffffff, 0x7fffffff};
        #pragma unroll 2
        for (int nt = 0; nt < 64; nt++) {
            float sc[8];
            score8(sh, afr, nt, lane, m4, sc);
            const int k0 = nt * 8 + 2 * m4;
            #pragma unroll
            for (int j = 0; j < 4; j++) {
                if (sc[2 * j] <= thr[j])
                    exact_update(sh, E, rowid[j], k0, Arow[j], bestS[j], bestk[j]);
                if (sc[2 * j + 1] <= thr[j])
                    exact_update(sh, E, rowid[j], k0 + 1, Arow[j], bestS[j], bestk[j]);
            }
        }

        // ---- lexicographic (S,k) reduce across the 4 lanes per row ----
        #pragma unroll
        for (int j = 0; j < 4; j++) {
            float S = bestS[j]; int k = bestk[j];
            #pragma unroll
            for (int off = 1; off <= 2; off <<= 1) {
                float oS = __shfl_xor_sync(0xffffffffu, S, off, 4);
                int   ok = __shfl_xor_sync(0xffffffffu, k, off, 4);
                if (oS < S || (oS == S && ok < k)) { S = oS; k = ok; }
            }
            if (m4 == 0) sh->kwin[rowid[j]] = k;
        }
        __syncthreads();

        // ---- emit: thread owns vector tid; coalesced stores ----
        {
            const int k = sh->kwin[tid];
            const float* er = E + k * DDIM;
            float* o = out + zq_off + (size_t)b * CHW + hw0 + tid;
            #pragma unroll
            for (int d = 0; d < DDIM; d++) {
                float zv = sh->zfp[d * TILE + tid];
                float t = er[d] - zv;              // fl(e - z)
                ls += t * t;
                o[(size_t)d * HW] = zv + t;        // fl(z + fl(e-z))
            }
        }
    }

    // ---- deterministic loss reduction + fused finalize ----
    #pragma unroll
    for (int off = 16; off; off >>= 1) ls += __shfl_down_sync(0xffffffffu, ls, off);
    if (lane == 0) sh->red[warp] = ls;
    __syncthreads();
    __shared__ unsigned int s_rank;
    if (tid == 0) {
        float t = 0.f;
        #pragma unroll
        for (int i = 0; i < WARPS; i++) t += sh->red[i];
        g_blocksums[blockIdx.x] = t;
        __threadfence();
        s_rank = atomicAdd(&g_done, 1u);
    }
    __syncthreads();
    if (s_rank == GRID - 1) {
        if (tid < 32) {
            double s = 0.0;
            for (int i = tid; i < GRID; i += 32) s += (double)g_blocksums[i];
            #pragma unroll
            for (int off = 16; off; off >>= 1) s += __shfl_down_sync(0xffffffffu, s, off);
            if (tid == 0) {
                if (zq_off >= 1) out[0] = (float)(s * (1.25 / 8388608.0));
                g_done = 0;   // reset for next graph replay
            }
        }
    }
}

extern "C" void kernel_launch(void* const* d_in, const int* in_sizes, int n_in,
                              void* d_out, int out_size)
{
    const float* inp = (const float*)d_in[0];  // [32,64,64,64] fp32
    const float* E   = (const float*)d_in[1];  // [512,64] fp32
    float* out = (float*)d_out;

    int zq_off = (out_size > ZQ_ELEMS) ? (out_size - ZQ_ELEMS) : 0;

    cudaFuncSetAttribute(vq_mma_kernel, cudaFuncAttributeMaxDynamicSharedMemorySize, SMEM_TOTAL);
    vq_mma_kernel<<<GRID, THREADS, SMEM_TOTAL>>>(inp, E, out, zq_off);
}

// round 8
// speedup vs baseline: 2.7910x; 1.8348x over previous
#include <cuda_runtime.h>
#include <cuda_bf16.h>
#include <cstdint>

// VectorQuantizer — bf16 mma.sync screening (two-pass) + lane-parallel exact fp32
// rescoring that bit-replicates the reference numerics:
//   dist_k = fl( fl(||z||^2 + ||e_k||^2) - 2*C_k ), C_k = ascending-d fmaf chain from 0
//   argmin first-index tie-break; Zq = fl(z + fl(e-z)); loss = 1.25*mean((e-z)^2)

typedef unsigned int u32;
typedef unsigned long long u64;

#define DDIM 64
#define KC 512
#define HW 4096
#define CHW 262144
#define NVEC 131072
#define THREADS 256
#define WARPS 8
#define GRID 148
#define TILE 256
#define NTILES (NVEC / TILE)     // 512
#define ZQ_ELEMS 8388608
#define LCAP 16                  // per-lane candidate slots

__device__ float g_blocksums[GRID];
__device__ unsigned int g_done = 0;

struct Smem {
    uint2 Bfrag[64 * 4 * 32];    // [ntile][ks][lane] bf16 fragments, 64KB
    float zfp[DDIM * TILE];      // [d][vector] exact z, 64KB
    float Bsh[KC];               // exact ||e_k||^2
    float An[TILE];              // exact ||z||^2
    u64   cbest[TILE];           // packed (S_bits<<32 | k), atomicMin
    u32   cand[THREADS * LCAP];  // per-lane candidate lists, 16KB
    float red[WARPS];
    float Bmax;
};
#define SMEM_TOTAL ((int)sizeof(Smem))

__device__ __forceinline__ u32 packbf(float lo, float hi) {
    u32 r; asm("cvt.rn.bf16x2.f32 %0, %1, %2;" : "=r"(r) : "f"(hi), "f"(lo)); return r;
}
__device__ __forceinline__ void mma16816(float c[4], const u32 a[4], const u32 b0, const u32 b1) {
    asm volatile(
        "mma.sync.aligned.m16n8k16.row.col.f32.bf16.bf16.f32 "
        "{%0,%1,%2,%3}, {%4,%5,%6,%7}, {%8,%9}, {%0,%1,%2,%3};"
        : "+f"(c[0]), "+f"(c[1]), "+f"(c[2]), "+f"(c[3])
        : "r"(a[0]), "r"(a[1]), "r"(a[2]), "r"(a[3]), "r"(b0), "r"(b1));
}

// 8 approx scores for n-tile nt (4 independent MMA chains, depth 2).
// Used identically in pass 1 and pass 2 -> identical score bits.
__device__ __forceinline__ void score8(const Smem* sh, const u32 afr[2][4][4],
                                       int nt, int lane, int m4, float sc[8]) {
    uint2 bf0 = sh->Bfrag[(nt * 4 + 0) * 32 + lane];
    uint2 bf1 = sh->Bfrag[(nt * 4 + 1) * 32 + lane];
    uint2 bf2 = sh->Bfrag[(nt * 4 + 2) * 32 + lane];
    uint2 bf3 = sh->Bfrag[(nt * 4 + 3) * 32 + lane];
    float c0a[4] = {0.f,0.f,0.f,0.f}, c0b[4] = {0.f,0.f,0.f,0.f};
    float c1a[4] = {0.f,0.f,0.f,0.f}, c1b[4] = {0.f,0.f,0.f,0.f};
    mma16816(c0a, afr[0][0], bf0.x, bf0.y);  mma16816(c1a, afr[1][0], bf0.x, bf0.y);
    mma16816(c0b, afr[0][2], bf2.x, bf2.y);  mma16816(c1b, afr[1][2], bf2.x, bf2.y);
    mma16816(c0a, afr[0][1], bf1.x, bf1.y);  mma16816(c1a, afr[1][1], bf1.x, bf1.y);
    mma16816(c0b, afr[0][3], bf3.x, bf3.y);  mma16816(c1b, afr[1][3], bf3.x, bf3.y);
    const int k0 = nt * 8 + 2 * m4;
    const float B0 = sh->Bsh[k0], B1 = sh->Bsh[k0 + 1];
    sc[0] = fmaf(-2.f, c0a[0] + c0b[0], B0);  sc[1] = fmaf(-2.f, c0a[1] + c0b[1], B1);
    sc[2] = fmaf(-2.f, c0a[2] + c0b[2], B0);  sc[3] = fmaf(-2.f, c0a[3] + c0b[3], B1);
    sc[4] = fmaf(-2.f, c1a[0] + c1b[0], B0);  sc[5] = fmaf(-2.f, c1a[1] + c1b[1], B1);
    sc[6] = fmaf(-2.f, c1a[2] + c1b[2], B0);  sc[7] = fmaf(-2.f, c1a[3] + c1b[3], B1);
}

// exact rescore (reference numerics) + deterministic lexicographic merge
__device__ __forceinline__ void exact_amin(Smem* sh, const float* __restrict__ E,
                                           int row, int k, float A) {
    const float* er = E + k * DDIM;
    float C = 0.f;
    #pragma unroll 16
    for (int d = 0; d < DDIM; d++) C = fmaf(sh->zfp[d * TILE + row], __ldg(er + d), C);
    float S = fmaf(-2.f, C, A + sh->Bsh[k]);
    u64 key = ((u64)__float_as_uint(S) << 32) | (u32)k;   // S>0 -> bits order-monotonic
    atomicMin(&sh->cbest[row], key);
}

__global__ void __launch_bounds__(THREADS, 1)
vq_mma_kernel(const float* __restrict__ inp, const float* __restrict__ E,
              float* __restrict__ out, int zq_off)
{
    extern __shared__ char smraw[];
    Smem* sh = (Smem*)smraw;

    const int tid = threadIdx.x;
    const int warp = tid >> 5;
    const int lane = tid & 31;
    const int m4 = lane & 3;
    const int qrow = lane >> 2;

    // ---- one-time staging: B fragments (bf16) + exact Bsh + Bmax ----
    for (int idx = tid; idx < 64 * 4 * 32; idx += THREADS) {
        int l = idx & 31, ks = (idx >> 5) & 3, nt = idx >> 7;
        int kc = nt * 8 + (l >> 2);
        int d0 = ks * 16 + 2 * (l & 3);
        const float* er = E + kc * DDIM;
        uint2 v;
        v.x = packbf(er[d0],     er[d0 + 1]);
        v.y = packbf(er[d0 + 8], er[d0 + 9]);
        sh->Bfrag[idx] = v;
    }
    for (int k = tid; k < KC; k += THREADS) {      // exact ||e||^2 (R2-verbatim)
        const float* er = E + k * DDIM;
        float bsum = 0.f;
        #pragma unroll
        for (int d = 0; d < DDIM; d++) { float e = er[d]; bsum = bsum + e * e; }
        sh->Bsh[k] = bsum;
    }
    __syncthreads();
    if (tid == 0) {
        float m = 0.f;
        for (int k = 0; k < KC; k++) m = fmaxf(m, sh->Bsh[k]);
        sh->Bmax = m;
    }
    __syncthreads();
    const float Bmax = sh->Bmax;

    float ls = 0.f;

    for (int tile = blockIdx.x; tile < NTILES; tile += GRID) {
        const int base = tile * TILE;
        const int b = base >> 12, hw0 = base & 4095;
        const float* zsrc = inp + (size_t)b * CHW + hw0;

        __syncthreads();   // protect reused smem across tiles
        #pragma unroll 8
        for (int d = 0; d < DDIM; d++)
            sh->zfp[d * TILE + tid] = __ldg(zsrc + (size_t)d * HW + tid);
        sh->cbest[tid] = 0xFFFFFFFFFFFFFFFFull;
        __syncthreads();
        {
            float A = 0.f;   // exact ||z||^2 ascending d (R2-verbatim)
            #pragma unroll
            for (int d = 0; d < DDIM; d++) { float a = sh->zfp[d * TILE + tid]; A = A + a * a; }
            sh->An[tid] = A;
        }
        __syncthreads();

        // ---- A fragments (this warp's 32 vectors, 2 m-tiles) ----
        u32 afr[2][4][4];
        const int r0g = warp * 32 + qrow;
        #pragma unroll
        for (int m = 0; m < 2; m++) {
            const int rA = r0g + m * 16, rB = rA + 8;
            #pragma unroll
            for (int ks = 0; ks < 4; ks++) {
                const int d0 = ks * 16 + 2 * m4;
                afr[m][ks][0] = packbf(sh->zfp[d0 * TILE + rA],       sh->zfp[(d0 + 1) * TILE + rA]);
                afr[m][ks][1] = packbf(sh->zfp[d0 * TILE + rB],       sh->zfp[(d0 + 1) * TILE + rB]);
                afr[m][ks][2] = packbf(sh->zfp[(d0 + 8) * TILE + rA], sh->zfp[(d0 + 9) * TILE + rA]);
                afr[m][ks][3] = packbf(sh->zfp[(d0 + 8) * TILE + rB], sh->zfp[(d0 + 9) * TILE + rB]);
            }
        }

        int rowid[4]; float Arow[4];
        #pragma unroll
        for (int j = 0; j < 4; j++) {
            rowid[j] = r0g + (j >> 1) * 16 + (j & 1) * 8;
            Arow[j] = sh->An[rowid[j]];
        }

        // ---- pass 1: branchless running min ----
        float runmin[4] = {3.402823466e38f, 3.402823466e38f, 3.402823466e38f, 3.402823466e38f};
        #pragma unroll 2
        for (int nt = 0; nt < 64; nt++) {
            float sc[8];
            score8(sh, afr, nt, lane, m4, sc);
            #pragma unroll
            for (int j = 0; j < 4; j++)
                runmin[j] = fminf(runmin[j], fminf(sc[2 * j], sc[2 * j + 1]));
        }
        float thr[4];
        #pragma unroll
        for (int j = 0; j < 4; j++) {
            float gm = runmin[j];
            gm = fminf(gm, __shfl_xor_sync(0xffffffffu, gm, 1, 4));
            gm = fminf(gm, __shfl_xor_sync(0xffffffffu, gm, 2, 4));
            thr[j] = gm + (0.025f * sqrtf(Arow[j] * Bmax) + 5e-5f);
        }

        // ---- pass 2: recompute, collect hits into per-lane smem lists ----
        int myCnt = 0;
        const u32 cbase = tid * LCAP;
        #pragma unroll 2
        for (int nt = 0; nt < 64; nt++) {
            float sc[8];
            score8(sh, afr, nt, lane, m4, sc);
            const int k0 = nt * 8 + 2 * m4;
            #pragma unroll
            for (int j = 0; j < 4; j++) {
                #pragma unroll
                for (int c = 0; c < 2; c++) {
                    if (sc[2 * j + c] <= thr[j]) {
                        if (myCnt < LCAP)
                            sh->cand[cbase + myCnt] = ((u32)rowid[j] << 16) | (u32)(k0 + c);
                        myCnt++;
                    }
                }
            }
        }

        const int ovf = (myCnt > LCAP);
        if (__any_sync(0xffffffffu, ovf)) {
            // fallback (P ~ 0): inline exact over every hit; min-merge is idempotent
            for (int nt = 0; nt < 64; nt++) {
                float sc[8];
                score8(sh, afr, nt, lane, m4, sc);
                const int k0 = nt * 8 + 2 * m4;
                #pragma unroll
                for (int j = 0; j < 4; j++) {
                    if (sc[2 * j]     <= thr[j]) exact_amin(sh, E, rowid[j], k0,     Arow[j]);
                    if (sc[2 * j + 1] <= thr[j]) exact_amin(sh, E, rowid[j], k0 + 1, Arow[j]);
                }
            }
        } else {
            // lane-parallel exact rescoring: each lane walks its own list
            int maxb = myCnt;
            #pragma unroll
            for (int off = 16; off; off >>= 1)
                maxb = max(maxb, __shfl_xor_sync(0xffffffffu, maxb, off));
            for (int i = 0; i < maxb; i++) {
                if (i < myCnt) {
                    u32 ent = sh->cand[cbase + i];
                    int row = ent >> 16, k = ent & 0xffff;
                    exact_amin(sh, E, row, k, sh->An[row]);
                }
            }
        }
        __syncthreads();

        // ---- emit: thread owns vector tid; coalesced stores ----
        {
            const int k = (int)(u32)(sh->cbest[tid] & 0xffffffffu);
            const float* er = E + k * DDIM;
            float* o = out + zq_off + (size_t)b * CHW + hw0 + tid;
            #pragma unroll
            for (int d = 0; d < DDIM; d++) {
                float zv = sh->zfp[d * TILE + tid];
                float t = er[d] - zv;              // fl(e - z)
                ls += t * t;
                o[(size_t)d * HW] = zv + t;        // fl(z + fl(e-z))
            }
        }
    }

    // ---- deterministic loss reduction + fused finalize ----
    #pragma unroll
    for (int off = 16; off; off >>= 1) ls += __shfl_down_sync(0xffffffffu, ls, off);
    if (lane == 0) sh->red[warp] = ls;
    __syncthreads();
    __shared__ unsigned int s_rank;
    if (tid == 0) {
        float t = 0.f;
        #pragma unroll
        for (int i = 0; i < WARPS; i++) t += sh->red[i];
        g_blocksums[blockIdx.x] = t;
        __threadfence();
        s_rank = atomicAdd(&g_done, 1u);
    }
    __syncthreads();
    if (s_rank == GRID - 1) {
        if (tid < 32) {
            double s = 0.0;
            for (int i = tid; i < GRID; i += 32) s += (double)g_blocksums[i];
            #pragma unroll
            for (int off = 16; off; off >>= 1) s += __shfl_down_sync(0xffffffffu, s, off);
            if (tid == 0) {
                if (zq_off >= 1) out[0] = (float)(s * (1.25 / 8388608.0));
                g_done = 0;   // reset for next graph replay
            }
        }
    }
}

extern "C" void kernel_launch(void* const* d_in, const int* in_sizes, int n_in,
                              void* d_out, int out_size)
{
    const float* inp = (const float*)d_in[0];  // [32,64,64,64] fp32
    const float* E   = (const float*)d_in[1];  // [512,64] fp32
    float* out = (float*)d_out;

    int zq_off = (out_size > ZQ_ELEMS) ? (out_size - ZQ_ELEMS) : 0;

    cudaFuncSetAttribute(vq_mma_kernel, cudaFuncAttributeMaxDynamicSharedMemorySize, SMEM_TOTAL);
    vq_mma_kernel<<<GRID, THREADS, SMEM_TOTAL>>>(inp, E, out, zq_off);
}

// round 9
// speedup vs baseline: 3.1404x; 1.1252x over previous
#include <cuda_runtime.h>
#include <cuda_bf16.h>
#include <cstdint>

// VectorQuantizer — bf16 mma.sync screening (two-pass) + lane-parallel exact fp32
// rescoring that bit-replicates the reference numerics:
//   dist_k = fl( fl(||z||^2 + ||e_k||^2) - 2*C_k ), C_k = ascending-d fmaf chain from 0
//   argmin first-index tie-break; Zq = fl(z + fl(e-z)); loss = 1.25*mean((e-z)^2)

typedef unsigned int u32;
typedef unsigned long long u64;

#define DDIM 64
#define KC 512
#define HW 4096
#define CHW 262144
#define NVEC 131072
#define THREADS 512
#define WARPS 16
#define GRID 148
#define TILE 256
#define TILEP 260                // padded zfp row stride -> conflict-free afr packing
#define NTILES (NVEC / TILE)     // 512
#define ZQ_ELEMS 8388608
#define LCAP 8                   // per-lane candidate slots

__device__ float g_blocksums[GRID];
__device__ unsigned int g_done = 0;

struct Smem {
    uint2 Bfrag[64 * 4 * 32];    // [ntile][ks][lane] bf16 fragments, 64KB
    float zfp[DDIM * TILEP];     // [d][vector] exact z (padded rows), 66560B
    float Bsh[KC];               // exact ||e_k||^2
    float An[TILE];              // exact ||z||^2
    u64   cbest[TILE];           // packed (S_bits<<32 | k), atomicMin
    u32   cand[THREADS * LCAP];  // per-lane candidate lists, 16KB
    float red[WARPS];
    float Bmax;
};
#define SMEM_TOTAL ((int)sizeof(Smem))

__device__ __forceinline__ u32 packbf(float lo, float hi) {
    u32 r; asm("cvt.rn.bf16x2.f32 %0, %1, %2;" : "=r"(r) : "f"(hi), "f"(lo)); return r;
}
__device__ __forceinline__ void mma16816(float c[4], const u32 a[4], const u32 b0, const u32 b1) {
    asm volatile(
        "mma.sync.aligned.m16n8k16.row.col.f32.bf16.bf16.f32 "
        "{%0,%1,%2,%3}, {%4,%5,%6,%7}, {%8,%9}, {%0,%1,%2,%3};"
        : "+f"(c[0]), "+f"(c[1]), "+f"(c[2]), "+f"(c[3])
        : "r"(a[0]), "r"(a[1]), "r"(a[2]), "r"(a[3]), "r"(b0), "r"(b1));
}

// 4 approx scores for this warp's m-tile at n-tile nt (2 independent MMA chains).
// Identical in pass 1 and pass 2 -> identical score bits.
__device__ __forceinline__ void score4(const Smem* sh, const u32 afr[4][4],
                                       int nt, int lane, int m4, float sc[4]) {
    uint2 bf0 = sh->Bfrag[(nt * 4 + 0) * 32 + lane];
    uint2 bf1 = sh->Bfrag[(nt * 4 + 1) * 32 + lane];
    uint2 bf2 = sh->Bfrag[(nt * 4 + 2) * 32 + lane];
    uint2 bf3 = sh->Bfrag[(nt * 4 + 3) * 32 + lane];
    float ca[4] = {0.f,0.f,0.f,0.f}, cb[4] = {0.f,0.f,0.f,0.f};
    mma16816(ca, afr[0], bf0.x, bf0.y);
    mma16816(cb, afr[2], bf2.x, bf2.y);
    mma16816(ca, afr[1], bf1.x, bf1.y);
    mma16816(cb, afr[3], bf3.x, bf3.y);
    const int k0 = nt * 8 + 2 * m4;
    const float B0 = sh->Bsh[k0], B1 = sh->Bsh[k0 + 1];
    sc[0] = fmaf(-2.f, ca[0] + cb[0], B0);  sc[1] = fmaf(-2.f, ca[1] + cb[1], B1);  // row rA
    sc[2] = fmaf(-2.f, ca[2] + cb[2], B0);  sc[3] = fmaf(-2.f, ca[3] + cb[3], B1);  // row rB
}

// exact rescore (reference numerics) + deterministic lexicographic merge
__device__ __forceinline__ void exact_amin(Smem* sh, const float* __restrict__ E,
                                           int row, int k, float A) {
    const float* er = E + k * DDIM;
    float C = 0.f;
    #pragma unroll 16
    for (int d = 0; d < DDIM; d++) C = fmaf(sh->zfp[d * TILEP + row], __ldg(er + d), C);
    float S = fmaf(-2.f, C, A + sh->Bsh[k]);
    u64 key = ((u64)__float_as_uint(S) << 32) | (u32)k;   // S>0 -> bits order-monotonic
    atomicMin(&sh->cbest[row], key);
}

__global__ void __launch_bounds__(THREADS, 1)
vq_mma_kernel(const float* __restrict__ inp, const float* __restrict__ E,
              float* __restrict__ out, int zq_off)
{
    extern __shared__ char smraw[];
    Smem* sh = (Smem*)smraw;

    const int tid = threadIdx.x;
    const int warp = tid >> 5;
    const int lane = tid & 31;
    const int m4 = lane & 3;
    const int qrow = lane >> 2;

    // ---- one-time staging: B fragments (bf16) + exact Bsh + Bmax ----
    for (int idx = tid; idx < 64 * 4 * 32; idx += THREADS) {
        int l = idx & 31, ks = (idx >> 5) & 3, nt = idx >> 7;
        int kc = nt * 8 + (l >> 2);
        int d0 = ks * 16 + 2 * (l & 3);
        const float* er = E + kc * DDIM;
        uint2 v;
        v.x = packbf(er[d0],     er[d0 + 1]);
        v.y = packbf(er[d0 + 8], er[d0 + 9]);
        sh->Bfrag[idx] = v;
    }
    {   // exact ||e||^2 (R2-verbatim), one code per thread
        const int k = tid;
        const float* er = E + k * DDIM;
        float bsum = 0.f;
        #pragma unroll
        for (int d = 0; d < DDIM; d++) { float e = er[d]; bsum = bsum + e * e; }
        sh->Bsh[k] = bsum;
    }
    __syncthreads();
    if (tid == 0) {
        float m = 0.f;
        for (int k = 0; k < KC; k++) m = fmaxf(m, sh->Bsh[k]);
        sh->Bmax = m;
    }
    __syncthreads();
    const float Bmax = sh->Bmax;

    float ls = 0.f;

    for (int tile = blockIdx.x; tile < NTILES; tile += GRID) {
        const int base = tile * TILE;
        const int b = base >> 12, hw0 = base & 4095;
        const float* zsrc = inp + (size_t)b * CHW + hw0;

        __syncthreads();   // protect reused smem across tiles
        for (int i = tid; i < DDIM * TILE; i += THREADS) {   // coalesced z staging
            int d = i >> 8, v = i & 255;
            sh->zfp[d * TILEP + v] = __ldg(zsrc + (size_t)d * HW + v);
        }
        if (tid < TILE) sh->cbest[tid] = 0xFFFFFFFFFFFFFFFFull;
        __syncthreads();
        if (tid < TILE) {
            float A = 0.f;   // exact ||z||^2 ascending d (R2-verbatim)
            #pragma unroll
            for (int d = 0; d < DDIM; d++) { float a = sh->zfp[d * TILEP + tid]; A = A + a * a; }
            sh->An[tid] = A;
        }
        __syncthreads();

        // ---- A fragments: this warp's 16 vectors (one m-tile) ----
        u32 afr[4][4];
        const int rA = warp * 16 + qrow;
        const int rB = rA + 8;
        #pragma unroll
        for (int ks = 0; ks < 4; ks++) {
            const int d0 = ks * 16 + 2 * m4;    // bank = 8*m4 + qrow: conflict-free
            afr[ks][0] = packbf(sh->zfp[d0 * TILEP + rA],       sh->zfp[(d0 + 1) * TILEP + rA]);
            afr[ks][1] = packbf(sh->zfp[d0 * TILEP + rB],       sh->zfp[(d0 + 1) * TILEP + rB]);
            afr[ks][2] = packbf(sh->zfp[(d0 + 8) * TILEP + rA], sh->zfp[(d0 + 9) * TILEP + rA]);
            afr[ks][3] = packbf(sh->zfp[(d0 + 8) * TILEP + rB], sh->zfp[(d0 + 9) * TILEP + rB]);
        }
        const float ArA = sh->An[rA], ArB = sh->An[rB];

        // ---- pass 1: branchless running min ----
        float rm0 = 3.402823466e38f, rm1 = 3.402823466e38f;
        #pragma unroll 4
        for (int nt = 0; nt < 64; nt++) {
            float sc[4];
            score4(sh, afr, nt, lane, m4, sc);
            rm0 = fminf(rm0, fminf(sc[0], sc[1]));
            rm1 = fminf(rm1, fminf(sc[2], sc[3]));
        }
        float gm0 = rm0, gm1 = rm1;
        gm0 = fminf(gm0, __shfl_xor_sync(0xffffffffu, gm0, 1, 4));
        gm0 = fminf(gm0, __shfl_xor_sync(0xffffffffu, gm0, 2, 4));
        gm1 = fminf(gm1, __shfl_xor_sync(0xffffffffu, gm1, 1, 4));
        gm1 = fminf(gm1, __shfl_xor_sync(0xffffffffu, gm1, 2, 4));
        const float thr0 = gm0 + (0.025f * sqrtf(ArA * Bmax) + 5e-5f);
        const float thr1 = gm1 + (0.025f * sqrtf(ArB * Bmax) + 5e-5f);

        // ---- pass 2: recompute, collect hits into per-lane smem lists ----
        int myCnt = 0;
        const u32 cbase = tid * LCAP;
        #pragma unroll 4
        for (int nt = 0; nt < 64; nt++) {
            float sc[4];
            score4(sh, afr, nt, lane, m4, sc);
            const int k0 = nt * 8 + 2 * m4;
            if (sc[0] <= thr0) { if (myCnt < LCAP) sh->cand[cbase + myCnt] = ((u32)rA << 16) | (u32)k0;       myCnt++; }
            if (sc[1] <= thr0) { if (myCnt < LCAP) sh->cand[cbase + myCnt] = ((u32)rA << 16) | (u32)(k0 + 1); myCnt++; }
            if (sc[2] <= thr1) { if (myCnt < LCAP) sh->cand[cbase + myCnt] = ((u32)rB << 16) | (u32)k0;       myCnt++; }
            if (sc[3] <= thr1) { if (myCnt < LCAP) sh->cand[cbase + myCnt] = ((u32)rB << 16) | (u32)(k0 + 1); myCnt++; }
        }

        const int ovf = (myCnt > LCAP);
        if (__any_sync(0xffffffffu, ovf)) {
            // fallback (P ~ 0): inline exact over every hit; min-merge is idempotent
            for (int nt = 0; nt < 64; nt++) {
                float sc[4];
                score4(sh, afr, nt, lane, m4, sc);
                const int k0 = nt * 8 + 2 * m4;
                if (sc[0] <= thr0) exact_amin(sh, E, rA, k0,     ArA);
                if (sc[1] <= thr0) exact_amin(sh, E, rA, k0 + 1, ArA);
                if (sc[2] <= thr1) exact_amin(sh, E, rB, k0,     ArB);
                if (sc[3] <= thr1) exact_amin(sh, E, rB, k0 + 1, ArB);
            }
        } else {
            // lane-parallel exact rescoring: each lane walks its own list
            int maxb = myCnt;
            #pragma unroll
            for (int off = 16; off; off >>= 1)
                maxb = max(maxb, __shfl_xor_sync(0xffffffffu, maxb, off));
            for (int i = 0; i < maxb; i++) {
                if (i < myCnt) {
                    u32 ent = sh->cand[cbase + i];
                    int row = ent >> 16, k = ent & 0xffff;
                    exact_amin(sh, E, row, k, sh->An[row]);
                }
            }
        }
        __syncthreads();

        // ---- emit: thread handles vector (tid&255), d-range (tid>>8)*32 ----
        {
            const int v = tid & 255;
            const int d0 = (tid >> 8) * 32;
            const int k = (int)(u32)(sh->cbest[v] & 0xffffffffu);
            const float* er = E + k * DDIM + d0;
            float* o = out + zq_off + (size_t)b * CHW + (size_t)d0 * HW + hw0 + v;
            #pragma unroll
            for (int d = 0; d < 32; d++) {
                float zv = sh->zfp[(d0 + d) * TILEP + v];
                float t = er[d] - zv;              // fl(e - z)
                ls += t * t;
                o[(size_t)d * HW] = zv + t;        // fl(z + fl(e-z))
            }
        }
    }

    // ---- deterministic loss reduction + fused finalize ----
    #pragma unroll
    for (int off = 16; off; off >>= 1) ls += __shfl_down_sync(0xffffffffu, ls, off);
    if (lane == 0) sh->red[warp] = ls;
    __syncthreads();
    __shared__ unsigned int s_rank;
    if (tid == 0) {
        float t = 0.f;
        #pragma unroll
        for (int i = 0; i < WARPS; i++) t += sh->red[i];
        g_blocksums[blockIdx.x] = t;
        __threadfence();
        s_rank = atomicAdd(&g_done, 1u);
    }
    __syncthreads();
    if (s_rank == GRID - 1) {
        if (tid < 32) {
            double s = 0.0;
            for (int i = tid; i < GRID; i += 32) s += (double)g_blocksums[i];
            #pragma unroll
            for (int off = 16; off; off >>= 1) s += __shfl_down_sync(0xffffffffu, s, off);
            if (tid == 0) {
                if (zq_off >= 1) out[0] = (float)(s * (1.25 / 8388608.0));
                g_done = 0;   // reset for next graph replay
            }
        }
    }
}

extern "C" void kernel_launch(void* const* d_in, const int* in_sizes, int n_in,
                              void* d_out, int out_size)
{
    const float* inp = (const float*)d_in[0];  // [32,64,64,64] fp32
    const float* E   = (const float*)d_in[1];  // [512,64] fp32
    float* out = (float*)d_out;

    int zq_off = (out_size > ZQ_ELEMS) ? (out_size - ZQ_ELEMS) : 0;

    cudaFuncSetAttribute(vq_mma_kernel, cudaFuncAttributeMaxDynamicSharedMemorySize, SMEM_TOTAL);
    vq_mma_kernel<<<GRID, THREADS, SMEM_TOTAL>>>(inp, E, out, zq_off);
}